// round 9
// baseline (speedup 1.0000x reference)
#include <cuda_runtime.h>

#define BATCH 4
#define NPTS 8192
#define G 32
#define NBINS (G * G)               // 1024
#define H 0.25f
#define HINV 4.0f
#define GLO -4.0f
#define SORT_THREADS 1024
#define NN_THREADS 256
#define NN_BLOCKS ((8 * NPTS) / NN_THREADS)   // 256
#define FULLMASK 0xffffffffu
#define BIG 3.0e38f

// Points sorted by (cx,cy) cell, quads (x,y,z,|p|^2), per (set,batch).
__device__ float4 g_pts[8][NPTS];
__device__ int g_cstart[8][NBINS + 1];
__device__ float g_bsum[NN_BLOCKS];
__device__ unsigned g_count;          // zero-init; reset each run

__device__ __forceinline__ int cellof(float v) {
    int c = (int)floorf((v - GLO) * HINV);
    return min(max(c, 0), G - 1);
}

// ---------------------------------------------------------------------------
// Counting sort by 2D cell (cx*32+cy). One block per (set,batch).
// ---------------------------------------------------------------------------
__global__ __launch_bounds__(SORT_THREADS)
void sort_kernel(const float* __restrict__ p1, const float* __restrict__ p2) {
    __shared__ unsigned hist[NBINS];       // 4 KB (1 bin per thread)
    __shared__ unsigned wtot[32];
    const int tid = threadIdx.x, lane = tid & 31, wid = tid >> 5;
    const int set = blockIdx.x >> 2;
    const int b = blockIdx.x & 3;
    const float* __restrict__ P = (set ? p2 : p1) + (size_t)b * NPTS * 3;

    hist[tid] = 0;
    __syncthreads();

    float xv[8], yv[8], zv[8];
#pragma unroll
    for (int k = 0; k < 8; k++) {
        int i = tid + k * SORT_THREADS;
        xv[k] = P[3 * i]; yv[k] = P[3 * i + 1]; zv[k] = P[3 * i + 2];
        atomicAdd(&hist[cellof(xv[k]) * G + cellof(yv[k])], 1u);
    }
    __syncthreads();

    unsigned s = hist[tid];
    unsigned v = s;
#pragma unroll
    for (int o = 1; o < 32; o <<= 1) {
        unsigned n = __shfl_up_sync(FULLMASK, v, o);
        if (lane >= o) v += n;
    }
    if (lane == 31) wtot[wid] = v;
    __syncthreads();
    if (tid < 32) {
        unsigned w = wtot[tid];
#pragma unroll
        for (int o = 1; o < 32; o <<= 1) {
            unsigned n = __shfl_up_sync(FULLMASK, w, o);
            if (tid >= o) w += n;
        }
        wtot[tid] = w;
    }
    __syncthreads();
    unsigned excl = v - s + (wid ? wtot[wid - 1] : 0u);
    __syncthreads();
    hist[tid] = excl;

    int* cs = g_cstart[blockIdx.x];
    cs[tid] = (int)excl;
    if (tid == 0) cs[NBINS] = NPTS;
    __syncthreads();                       // cs published before scatter mutates hist

    float4* dst = g_pts[blockIdx.x];
#pragma unroll
    for (int k = 0; k < 8; k++) {
        unsigned pos = atomicAdd(&hist[cellof(xv[k]) * G + cellof(yv[k])], 1u);
        dst[pos] = make_float4(xv[k], yv[k], zv[k],
            xv[k] * xv[k] + yv[k] * yv[k] + zv[k] * zv[k]);
    }
}

// ---------------------------------------------------------------------------
// NN: warp-cooperative box scan. Each warp owns 32 consecutive cell-sorted
// queries; scans the warp-union candidate box ONCE with warp-uniform
// broadcast loads; expands the box ring-by-ring until all lanes certify.
// ---------------------------------------------------------------------------
__global__ __launch_bounds__(NN_THREADS)
void nn_kernel(float* __restrict__ out) {
    __shared__ float sred[8];
    __shared__ bool s_last;

    const int tid = threadIdx.x, lane = tid & 31, wid = tid >> 5;
    const int db  = blockIdx.y;            // dir*4 + b
    const int dir = db >> 2, b = db & 3;
    const float4* __restrict__ Q = g_pts[(dir ? 4 : 0) + b];
    const float4* __restrict__ T = g_pts[(dir ? 0 : 4) + b];
    const int* __restrict__ cs   = g_cstart[(dir ? 0 : 4) + b];

    const int qi = blockIdx.x * NN_THREADS + tid;   // cell-sorted query index
    const float4 q = Q[qi];
    const float qx = q.x, qy = q.y, qsq = q.w;
    const float m2x = -2.f * q.x, m2y = -2.f * q.y, m2z = -2.f * q.z;
    const int cx = cellof(qx), cy = cellof(qy);

    float bestv = BIG;                     // min of (|t|^2 - 2 q.t)

    // Warp-uniform scan of one column's contiguous cell range [ylo..yhi].
    auto scan_run = [&](int xc, int ylo, int yhi) {
        int i = cs[xc * G + ylo];
        const int e = cs[xc * G + yhi + 1];
        float b0 = bestv, b1 = BIG, b2 = BIG, b3 = BIG;
        for (; i + 3 < e; i += 4) {        // warp-uniform i: broadcast loads
            float4 t0 = T[i], t1 = T[i + 1], t2 = T[i + 2], t3 = T[i + 3];
            b0 = fminf(b0, fmaf(m2x, t0.x, fmaf(m2y, t0.y, fmaf(m2z, t0.z, t0.w))));
            b1 = fminf(b1, fmaf(m2x, t1.x, fmaf(m2y, t1.y, fmaf(m2z, t1.z, t1.w))));
            b2 = fminf(b2, fmaf(m2x, t2.x, fmaf(m2y, t2.y, fmaf(m2z, t2.z, t2.w))));
            b3 = fminf(b3, fmaf(m2x, t3.x, fmaf(m2y, t3.y, fmaf(m2z, t3.z, t3.w))));
        }
        for (; i < e; i++) {
            float4 t = T[i];
            b0 = fminf(b0, fmaf(m2x, t.x, fmaf(m2y, t.y, fmaf(m2z, t.z, t.w))));
        }
        bestv = fminf(fminf(b0, b1), fminf(b2, b3));
    };

    // Warp-union initial box (cells of all 32 queries, +1 ring).
    int x0 = max((int)__reduce_min_sync(FULLMASK, (unsigned)cx) - 1, 0);
    int x1 = min((int)__reduce_max_sync(FULLMASK, (unsigned)cx) + 1, G - 1);
    int y0 = max((int)__reduce_min_sync(FULLMASK, (unsigned)cy) - 1, 0);
    int y1 = min((int)__reduce_max_sync(FULLMASK, (unsigned)cy) + 1, G - 1);

    for (int xc = x0; xc <= x1; xc++) scan_run(xc, y0, y1);

    // Expand ring-by-ring until every lane's certificate holds.
    for (;;) {
        float mlx = (x0 == 0)     ? BIG : qx - (GLO + x0 * H);
        float mhx = (x1 == G - 1) ? BIG : (GLO + (x1 + 1) * H) - qx;
        float mly = (y0 == 0)     ? BIG : qy - (GLO + y0 * H);
        float mhy = (y1 == G - 1) ? BIG : (GLO + (y1 + 1) * H) - qy;
        float m = fminf(fminf(mlx, mhx), fminf(mly, mhy)) - 1e-4f;
        bool done = (m > 0.f) && (m * m >= bestv + qsq);
        if (__all_sync(FULLMASK, done)) break;
        if (x0 == 0 && y0 == 0 && x1 == G - 1 && y1 == G - 1) break;

        const int nx0 = max(x0 - 1, 0), nx1 = min(x1 + 1, G - 1);
        const int ny0 = max(y0 - 1, 0), ny1 = min(y1 + 1, G - 1);
        if (nx0 < x0) scan_run(nx0, ny0, ny1);
        if (nx1 > x1) scan_run(nx1, ny0, ny1);
        if (ny0 < y0) for (int xc = x0; xc <= x1; xc++) scan_run(xc, ny0, ny0);
        if (ny1 > y1) for (int xc = x0; xc <= x1; xc++) scan_run(xc, ny1, ny1);
        x0 = nx0; x1 = nx1; y0 = ny0; y1 = ny1;
    }

    float d2 = bestv + qsq;                // exact min squared distance

    // Reduction: per-block partials, last block folds all.
#pragma unroll
    for (int o = 16; o; o >>= 1) d2 += __shfl_down_sync(FULLMASK, d2, o);
    if (lane == 0) sred[wid] = d2;
    __syncthreads();
    if (tid == 0) {
        float w = 0.f;
#pragma unroll
        for (int i = 0; i < NN_THREADS / 32; i++) w += sred[i];
        g_bsum[blockIdx.y * gridDim.x + blockIdx.x] = w;
        __threadfence();
        unsigned t = atomicAdd(&g_count, 1u);
        s_last = (t == NN_BLOCKS - 1);
    }
    __syncthreads();

    if (s_last) {
        __threadfence();
        float w = g_bsum[tid];             // NN_BLOCKS == NN_THREADS == 256
#pragma unroll
        for (int o = 16; o; o >>= 1) w += __shfl_down_sync(FULLMASK, w, o);
        if (lane == 0) sred[wid] = w;
        __syncthreads();
        if (tid == 0) {
            float tot = 0.f;
#pragma unroll
            for (int i = 0; i < NN_THREADS / 32; i++) tot += sred[i];
            out[0] = tot;
            g_count = 0u;                  // reset for next graph replay
        }
    }
}

extern "C" void kernel_launch(void* const* d_in, const int* in_sizes, int n_in,
                              void* d_out, int out_size) {
    const float* p1 = (const float*)d_in[0];
    const float* p2 = (const float*)d_in[1];
    float* out = (float*)d_out;

    sort_kernel<<<8, SORT_THREADS>>>(p1, p2);
    nn_kernel<<<dim3(NPTS / NN_THREADS, 8), NN_THREADS>>>(out);
}

// round 10
// speedup vs baseline: 2.3699x; 2.3699x over previous
#include <cuda_runtime.h>

#define BATCH 4
#define NPTS 8192
#define BINS 8192
#define BHINV (8192.0f / 12.0f)
#define BGLO -6.0f
#define SORT_THREADS 1024
#define NN_THREADS 256
#define FULLMASK 0xffffffffu
#define BIG 3.0e38f
#define TOTQ (8 * NPTS)

// Sorted-by-x quads (x,y,z,|p|^2) per (set*4+batch); bucket starts.
__device__ float4 g_pts[8][NPTS];
__device__ int g_cstart[8][BINS + 1];
__device__ unsigned g_key[TOTQ];     // enckey(val); 0 == +inf identity (zero-init)

__device__ __forceinline__ int bucket(float v) {
    int c = (int)floorf((v - BGLO) * BHINV);
    return min(max(c, 0), BINS - 1);
}
__device__ __forceinline__ unsigned enckey(float f) {
    unsigned u = __float_as_uint(f);
    u = (u & 0x80000000u) ? ~u : (u | 0x80000000u);
    return ~u;
}
__device__ __forceinline__ float deckey(unsigned k) {
    unsigned u = ~k;
    return __uint_as_float((u & 0x80000000u) ? (u & 0x7FFFFFFFu) : ~u);
}

// ---------------------------------------------------------------------------
// Counting sort by x-bucket. One block per (set,batch). Also zeroes out[0].
// ---------------------------------------------------------------------------
__global__ __launch_bounds__(SORT_THREADS)
void sort_kernel(const float* __restrict__ p1, const float* __restrict__ p2,
                 float* __restrict__ out) {
    __shared__ unsigned hist[BINS];
    __shared__ unsigned wtot[32];
    const int tid = threadIdx.x, lane = tid & 31, wid = tid >> 5;
    const int set = blockIdx.x >> 2;
    const int b = blockIdx.x & 3;
    const float* __restrict__ P = (set ? p2 : p1) + (size_t)b * NPTS * 3;

    if (blockIdx.x == 0 && tid == 0) out[0] = 0.0f;

    for (int i = tid; i < BINS; i += SORT_THREADS) hist[i] = 0;
    __syncthreads();

    float xv[8], yv[8], zv[8];
#pragma unroll
    for (int k = 0; k < 8; k++) {
        int i = tid + k * SORT_THREADS;
        xv[k] = P[3 * i]; yv[k] = P[3 * i + 1]; zv[k] = P[3 * i + 2];
        atomicAdd(&hist[bucket(xv[k])], 1u);
    }
    __syncthreads();

    // Exclusive scan over 8192 bins (8/thread + hierarchical warp scan).
    const int base = tid * 8;
    unsigned loc[8], s = 0;
#pragma unroll
    for (int j = 0; j < 8; j++) { loc[j] = s; s += hist[base + j]; }
    unsigned v = s;
#pragma unroll
    for (int o = 1; o < 32; o <<= 1) {
        unsigned n = __shfl_up_sync(FULLMASK, v, o);
        if (lane >= o) v += n;
    }
    if (lane == 31) wtot[wid] = v;
    __syncthreads();
    if (tid < 32) {
        unsigned w = wtot[tid];
#pragma unroll
        for (int o = 1; o < 32; o <<= 1) {
            unsigned n = __shfl_up_sync(FULLMASK, w, o);
            if (tid >= o) w += n;
        }
        wtot[tid] = w;
    }
    __syncthreads();
    unsigned thr_excl = v - s + (wid ? wtot[wid - 1] : 0u);
    __syncthreads();
#pragma unroll
    for (int j = 0; j < 8; j++) hist[base + j] = thr_excl + loc[j];
    __syncthreads();

    // Publish bucket starts BEFORE scatter mutates hist.
    int* cs = g_cstart[blockIdx.x];
#pragma unroll
    for (int j = 0; j < 8; j++) cs[base + j] = (int)hist[base + j];
    if (tid == 0) cs[BINS] = NPTS;
    __syncthreads();

    float4* dst = g_pts[blockIdx.x];
#pragma unroll
    for (int k = 0; k < 8; k++) {
        unsigned pos = atomicAdd(&hist[bucket(xv[k])], 1u);
        dst[pos] = make_float4(xv[k], yv[k], zv[k],
            xv[k] * xv[k] + yv[k] * yv[k] + zv[k] * zv[k]);
    }
}

// ---------------------------------------------------------------------------
// NN: phase A (fixed 128-rank window -> upper bound Rw), then phase B:
// fixed-range quarter scans by 4 warps per 32-query group. No certificates,
// no votes in hot loops -> pure pipelined throughput.
// ---------------------------------------------------------------------------
__global__ __launch_bounds__(NN_THREADS)
void nn_kernel() {
    const int tid = threadIdx.x, lane = tid & 31, wid = tid >> 5;
    const int wg = wid >> 2;                // group within block (0,1)
    const int w  = wid & 3;                 // quarter index
    const int db = blockIdx.y;              // query array index (0..7)
    const float4* __restrict__ Q = g_pts[db];
    const float4* __restrict__ T = g_pts[db ^ 4];
    const int* __restrict__ cs   = g_cstart[db ^ 4];

    const int grank = (blockIdx.x * 2 + wg) * 32;   // group's first query rank
    const int qi = grank + lane;
    const float4 q = Q[qi];
    const float qx = q.x, qsq = q.w;
    const float m2x = -2.f * q.x, m2y = -2.f * q.y, m2z = -2.f * q.z;

    float b0 = BIG, b1 = BIG, b2 = BIG, b3 = BIG;

    // ---- Phase A: fixed 128-target rank window (upper bound) ----
    const int ws = min(max(grank + 16 - 64, 0), NPTS - 128);
#pragma unroll 4
    for (int j = 0; j < 128; j += 4) {
        float4 t0 = T[ws + j],     t1 = T[ws + j + 1];
        float4 t2 = T[ws + j + 2], t3 = T[ws + j + 3];
        b0 = fminf(b0, fmaf(m2x, t0.x, fmaf(m2y, t0.y, fmaf(m2z, t0.z, t0.w))));
        b1 = fminf(b1, fmaf(m2x, t1.x, fmaf(m2y, t1.y, fmaf(m2z, t1.z, t1.w))));
        b2 = fminf(b2, fmaf(m2x, t2.x, fmaf(m2y, t2.y, fmaf(m2z, t2.z, t2.w))));
        b3 = fminf(b3, fmaf(m2x, t3.x, fmaf(m2y, t3.y, fmaf(m2z, t3.z, t3.w))));
    }
    float bv = fminf(fminf(b0, b1), fminf(b2, b3));

    // ---- Bound: Rw = max over lanes of sqrt(d2_upper); range in x ----
    float d2u = fmaxf(bv + qsq, 0.0f);
    float xmn = qx, xmx = qx;
#pragma unroll
    for (int o = 16; o; o >>= 1) {
        d2u = fmaxf(d2u, __shfl_xor_sync(FULLMASK, d2u, o));
        xmn = fminf(xmn, __shfl_xor_sync(FULLMASK, xmn, o));
        xmx = fmaxf(xmx, __shfl_xor_sync(FULLMASK, xmx, o));
    }
    const float Rw = sqrtf(d2u) * 1.001f + 1e-3f;
    const int blo = bucket(xmn - Rw), bhi = bucket(xmx + Rw);
    const int s = cs[blo], e = cs[bhi + 1];
    const int len = e - s;
    const int q0 = s + (len * w) / 4;
    const int q1 = s + (len * (w + 1)) / 4;

    // ---- Phase B: fixed quarter-range scan, 4 accumulators, no exits ----
    b0 = bv; b1 = BIG; b2 = BIG; b3 = BIG;
    int i = q0;
    for (; i + 3 < q1; i += 4) {
        float4 t0 = T[i],     t1 = T[i + 1];
        float4 t2 = T[i + 2], t3 = T[i + 3];
        b0 = fminf(b0, fmaf(m2x, t0.x, fmaf(m2y, t0.y, fmaf(m2z, t0.z, t0.w))));
        b1 = fminf(b1, fmaf(m2x, t1.x, fmaf(m2y, t1.y, fmaf(m2z, t1.z, t1.w))));
        b2 = fminf(b2, fmaf(m2x, t2.x, fmaf(m2y, t2.y, fmaf(m2z, t2.z, t2.w))));
        b3 = fminf(b3, fmaf(m2x, t3.x, fmaf(m2y, t3.y, fmaf(m2z, t3.z, t3.w))));
    }
    for (; i < q1; i++) {
        float4 t = T[i];
        b0 = fminf(b0, fmaf(m2x, t.x, fmaf(m2y, t.y, fmaf(m2z, t.z, t.w))));
    }
    bv = fminf(fminf(b0, b1), fminf(b2, b3));

    atomicMax(&g_key[db * NPTS + qi], enckey(bv));
}

// ---------------------------------------------------------------------------
// Finish: d2 = deckey + |q|^2, sum, atomicAdd; reset keys for graph replay.
// ---------------------------------------------------------------------------
__global__ __launch_bounds__(256)
void finish_kernel(float* __restrict__ out) {
    const int gid = blockIdx.x * 256 + threadIdx.x;     // over 65536
    const int db = gid >> 13, qi = gid & (NPTS - 1);
    float v = deckey(g_key[gid]) + g_pts[db][qi].w;
    g_key[gid] = 0u;

    __shared__ float sred[8];
#pragma unroll
    for (int o = 16; o; o >>= 1) v += __shfl_down_sync(FULLMASK, v, o);
    if ((threadIdx.x & 31) == 0) sred[threadIdx.x >> 5] = v;
    __syncthreads();
    if (threadIdx.x == 0) {
        float t = 0.f;
#pragma unroll
        for (int i = 0; i < 8; i++) t += sred[i];
        atomicAdd(out, t);
    }
}

extern "C" void kernel_launch(void* const* d_in, const int* in_sizes, int n_in,
                              void* d_out, int out_size) {
    const float* p1 = (const float*)d_in[0];
    const float* p2 = (const float*)d_in[1];
    float* out = (float*)d_out;

    sort_kernel<<<8, SORT_THREADS>>>(p1, p2, out);
    nn_kernel<<<dim3(128, 8), NN_THREADS>>>();          // 8192 warps
    finish_kernel<<<TOTQ / 256, 256>>>(out);
}

// round 11
// speedup vs baseline: 4.0814x; 1.7222x over previous
#include <cuda_runtime.h>

#define NPTS 8192
#define BINS 8192
#define BHINV (8192.0f / 12.0f)
#define BGLO -6.0f
#define TILE 512
#define NTILE (NPTS / TILE)          // 16
#define PB_THREADS 128
#define QPT 4                        // TILE / PB_THREADS
#define FULLMASK 0xffffffffu
#define BIG 3.0e38f
#define TOTQ (8 * NPTS)

typedef unsigned long long ull;

__device__ float4 g_pts[8][NPTS];        // sorted-by-x quads (x,y,z,|p|^2)
__device__ unsigned g_hist[8][BINS];     // zero-init; re-zeroed by scan each run
__device__ int g_coff[8][BINS];          // scatter offsets (rebuilt each run)
__device__ float g_dmax[8][NTILE];       // per-query-tile upper bound d2
__device__ unsigned g_key[TOTQ];         // enckey(bv); 0 identity; reset by finish

__device__ __forceinline__ int bucket(float v) {
    int c = (int)floorf((v - BGLO) * BHINV);
    return min(max(c, 0), BINS - 1);
}
__device__ __forceinline__ unsigned enckey(float f) {
    unsigned u = __float_as_uint(f);
    u = (u & 0x80000000u) ? ~u : (u | 0x80000000u);
    return ~u;
}
__device__ __forceinline__ float deckey(unsigned k) {
    unsigned u = ~k;
    return __uint_as_float((u & 0x80000000u) ? (u & 0x7FFFFFFFu) : ~u);
}
__device__ __forceinline__ ull pack2(float a, float b) {
    ull r;
    asm("mov.b64 %0, {%1, %2};" : "=l"(r) : "f"(a), "f"(b));
    return r;
}
// Proven R1 packed step: d2(lo,hi) for 2 targets, fused mins.
__device__ __forceinline__ void step(float& ma, float& mb,
                                     ull qx, ull qy, ull qz,
                                     ull n0, ull n1, ull n2, ull cc) {
    asm("{\n\t"
        ".reg .b64 t;\n\t"
        ".reg .f32 lo, hi;\n\t"
        "fma.rn.f32x2 t, %2, %5, %8;\n\t"
        "fma.rn.f32x2 t, %3, %6, t;\n\t"
        "fma.rn.f32x2 t, %4, %7, t;\n\t"
        "mov.b64 {lo, hi}, t;\n\t"
        "min.f32 %0, %0, lo;\n\t"
        "min.f32 %1, %1, hi;\n\t"
        "}"
        : "+f"(ma), "+f"(mb)
        : "l"(qx), "l"(qy), "l"(qz), "l"(n0), "l"(n1), "l"(n2), "l"(cc));
}

// ---- Sort k1: histogram (64 blocks) ----------------------------------------
__global__ __launch_bounds__(256)
void hist_kernel(const float* __restrict__ p1, const float* __restrict__ p2) {
    const int db = blockIdx.x >> 3, chunk = blockIdx.x & 7;
    const float* __restrict__ P =
        ((db >> 2) ? p2 : p1) + (size_t)(db & 3) * NPTS * 3;
#pragma unroll
    for (int k = 0; k < 4; k++) {
        int i = chunk * 1024 + threadIdx.x + k * 256;
        atomicAdd(&g_hist[db][bucket(P[3 * i])], 1u);
    }
}

// ---- Sort k2: scan hist -> g_coff; zero hist; zero out[0] -------------------
__global__ __launch_bounds__(1024)
void scan_kernel(float* __restrict__ out) {
    __shared__ unsigned wtot[32];
    const int db = blockIdx.x, tid = threadIdx.x, lane = tid & 31, wid = tid >> 5;
    if (db == 0 && tid == 0) out[0] = 0.0f;

    const int base = tid * 8;
    unsigned h[8], loc[8], s = 0;
#pragma unroll
    for (int j = 0; j < 8; j++) {
        h[j] = g_hist[db][base + j];
        g_hist[db][base + j] = 0u;           // reset for next replay
        loc[j] = s; s += h[j];
    }
    unsigned v = s;
#pragma unroll
    for (int o = 1; o < 32; o <<= 1) {
        unsigned n = __shfl_up_sync(FULLMASK, v, o);
        if (lane >= o) v += n;
    }
    if (lane == 31) wtot[wid] = v;
    __syncthreads();
    if (tid < 32) {
        unsigned w = wtot[tid];
#pragma unroll
        for (int o = 1; o < 32; o <<= 1) {
            unsigned n = __shfl_up_sync(FULLMASK, w, o);
            if (tid >= o) w += n;
        }
        wtot[tid] = w;
    }
    __syncthreads();
    unsigned excl = v - s + (wid ? wtot[wid - 1] : 0u);
#pragma unroll
    for (int j = 0; j < 8; j++) g_coff[db][base + j] = (int)(excl + loc[j]);
}

// ---- Sort k3: scatter quads (64 blocks) -------------------------------------
__global__ __launch_bounds__(256)
void scatter_kernel(const float* __restrict__ p1, const float* __restrict__ p2) {
    const int db = blockIdx.x >> 3, chunk = blockIdx.x & 7;
    const float* __restrict__ P =
        ((db >> 2) ? p2 : p1) + (size_t)(db & 3) * NPTS * 3;
#pragma unroll
    for (int k = 0; k < 4; k++) {
        int i = chunk * 1024 + threadIdx.x + k * 256;
        float x = P[3 * i], y = P[3 * i + 1], z = P[3 * i + 2];
        int pos = atomicAdd(&g_coff[db][bucket(x)], 1);
        g_pts[db][pos] = make_float4(x, y, z, x * x + y * y + z * z);
    }
}

// ---- Pass A: per-query-tile upper bound from fixed 256-rank window ----------
__global__ __launch_bounds__(256)
void bound_kernel() {
    __shared__ float sred[8];
    const int tid = threadIdx.x, lane = tid & 31, wid = tid >> 5;
    const int qt = blockIdx.x, db = blockIdx.y;
    const float4* __restrict__ Q = g_pts[db];
    const float4* __restrict__ T = g_pts[db ^ 4];

    const int ws = min(max(qt * TILE + TILE / 2 - 128, 0), NPTS - 256);
    float dm = 0.0f;
#pragma unroll
    for (int k = 0; k < 2; k++) {
        const float4 q = Q[qt * TILE + tid + k * 256];
        const float m2x = -2.f * q.x, m2y = -2.f * q.y, m2z = -2.f * q.z;
        float a0 = BIG, a1 = BIG;
        for (int j = 0; j < 256; j += 2) {
            float4 t0 = T[ws + j], t1 = T[ws + j + 1];
            a0 = fminf(a0, fmaf(m2x, t0.x, fmaf(m2y, t0.y, fmaf(m2z, t0.z, t0.w))));
            a1 = fminf(a1, fmaf(m2x, t1.x, fmaf(m2y, t1.y, fmaf(m2z, t1.z, t1.w))));
        }
        dm = fmaxf(dm, fminf(a0, a1) + q.w);
    }
#pragma unroll
    for (int o = 16; o; o >>= 1) dm = fmaxf(dm, __shfl_xor_sync(FULLMASK, dm, o));
    if (lane == 0) sred[wid] = dm;
    __syncthreads();
    if (tid == 0) {
        float m = 0.f;
#pragma unroll
        for (int i = 0; i < 8; i++) m = fmaxf(m, sred[i]);
        g_dmax[db][qt] = m;
    }
}

// ---- Pass B: R1 tile loop with block-level x-gap pruning ---------------------
__global__ __launch_bounds__(PB_THREADS)
void tile_kernel() {
    const int qt = blockIdx.x >> 4, ts = blockIdx.x & 15;
    const int db = blockIdx.y;
    const float4* __restrict__ Q = g_pts[db];
    const float4* __restrict__ T = g_pts[db ^ 4];

    // Prune: x-gap between tiles vs tile bound (witness tile always survives).
    {
        const float qlo = Q[qt * TILE].x, qhi = Q[qt * TILE + TILE - 1].x;
        const float tlo = T[ts * TILE].x, thi = T[ts * TILE + TILE - 1].x;
        const float gap = fmaxf(0.f, fmaxf(tlo - qhi, qlo - thi));
        if (gap * gap > g_dmax[db][qt] * 1.0001f + 1e-6f) return;
    }

    __shared__ __align__(16) ull s_t[TILE / 2][4];   // 8 KB packed pairs
    const int tid = threadIdx.x;

    // Stage target tile: per pair -> (n0,n1,n2,cc) packed f32x2.
#pragma unroll
    for (int k = 0; k < 2; k++) {
        const int i = tid + k * PB_THREADS;          // pair index 0..255
        float4 ta = T[ts * TILE + 2 * i];
        float4 tc = T[ts * TILE + 2 * i + 1];
        ulonglong2* d = (ulonglong2*)s_t[i];
        d[0] = make_ulonglong2(pack2(-2.0f * ta.x, -2.0f * tc.x),
                               pack2(-2.0f * ta.y, -2.0f * tc.y));
        d[1] = make_ulonglong2(pack2(-2.0f * ta.z, -2.0f * tc.z),
                               pack2(ta.w, tc.w));
    }

    ull qx[QPT], qy[QPT], qz[QPT];
    float ma[QPT], mb[QPT];
#pragma unroll
    for (int k = 0; k < QPT; k++) {
        const float4 q = Q[qt * TILE + tid + k * PB_THREADS];
        qx[k] = pack2(q.x, q.x);
        qy[k] = pack2(q.y, q.y);
        qz[k] = pack2(q.z, q.z);
        ma[k] = BIG; mb[k] = BIG;
    }
    __syncthreads();

    const ulonglong2* sm = (const ulonglong2*)&s_t[0][0];
#pragma unroll 2
    for (int j = 0; j < TILE / 2; j++) {
        ulonglong2 v0 = sm[2 * j];       // (n0,n1) LDS.128 broadcast
        ulonglong2 v1 = sm[2 * j + 1];   // (n2,cc)
#pragma unroll
        for (int k = 0; k < QPT; k++)
            step(ma[k], mb[k], qx[k], qy[k], qz[k], v0.x, v0.y, v1.x, v1.y);
    }

    unsigned* gk = g_key + db * NPTS + qt * TILE;
#pragma unroll
    for (int k = 0; k < QPT; k++)
        atomicMax(&gk[tid + k * PB_THREADS], enckey(fminf(ma[k], mb[k])));
}

// ---- Finish: add |q|^2, reduce, atomicAdd; reset keys ------------------------
__global__ __launch_bounds__(256)
void finish_kernel(float* __restrict__ out) {
    const int gid = blockIdx.x * 256 + threadIdx.x;
    const int db = gid >> 13, qi = gid & (NPTS - 1);
    float v = deckey(g_key[gid]) + g_pts[db][qi].w;
    g_key[gid] = 0u;

    __shared__ float sred[8];
#pragma unroll
    for (int o = 16; o; o >>= 1) v += __shfl_down_sync(FULLMASK, v, o);
    if ((threadIdx.x & 31) == 0) sred[threadIdx.x >> 5] = v;
    __syncthreads();
    if (threadIdx.x == 0) {
        float t = 0.f;
#pragma unroll
        for (int i = 0; i < 8; i++) t += sred[i];
        atomicAdd(out, t);
    }
}

extern "C" void kernel_launch(void* const* d_in, const int* in_sizes, int n_in,
                              void* d_out, int out_size) {
    const float* p1 = (const float*)d_in[0];
    const float* p2 = (const float*)d_in[1];
    float* out = (float*)d_out;

    hist_kernel<<<64, 256>>>(p1, p2);
    scan_kernel<<<8, 1024>>>(out);
    scatter_kernel<<<64, 256>>>(p1, p2);
    bound_kernel<<<dim3(NTILE, 8), 256>>>();
    tile_kernel<<<dim3(NTILE * NTILE, 8), PB_THREADS>>>();
    finish_kernel<<<TOTQ / 256, 256>>>(out);
}

// round 12
// speedup vs baseline: 5.6137x; 1.3754x over previous
#include <cuda_runtime.h>

#define NPTS 8192
#define BINS 8192
#define BHINV (8192.0f / 12.0f)
#define BGLO -6.0f
#define TILE 256
#define NTILE (NPTS / TILE)          // 32
#define PB_THREADS 128
#define QPT 2                        // TILE / PB_THREADS
#define FULLMASK 0xffffffffu
#define BIG 3.0e38f
#define TOTQ (8 * NPTS)

typedef unsigned long long ull;

__device__ float4 g_pts[8][NPTS];        // sorted-by-x quads (x,y,z,|p|^2)
__device__ unsigned g_hist[8][BINS];     // zero-init; re-zeroed by scan each run
__device__ int g_coff[8][BINS];          // scatter offsets (rebuilt each run)
__device__ float g_dmax[8][NTILE];       // per-query-tile upper bound d2
__device__ unsigned g_key[TOTQ];         // enckey(bv); 0 identity; reset by finish

__device__ __forceinline__ int bucket(float v) {
    int c = (int)floorf((v - BGLO) * BHINV);
    return min(max(c, 0), BINS - 1);
}
__device__ __forceinline__ unsigned enckey(float f) {
    unsigned u = __float_as_uint(f);
    u = (u & 0x80000000u) ? ~u : (u | 0x80000000u);
    return ~u;
}
__device__ __forceinline__ float deckey(unsigned k) {
    unsigned u = ~k;
    return __uint_as_float((u & 0x80000000u) ? (u & 0x7FFFFFFFu) : ~u);
}
__device__ __forceinline__ ull pack2(float a, float b) {
    ull r;
    asm("mov.b64 %0, {%1, %2};" : "=l"(r) : "f"(a), "f"(b));
    return r;
}
// Proven R1 packed step: d2(lo,hi) for 2 targets, fused mins.
__device__ __forceinline__ void step(float& ma, float& mb,
                                     ull qx, ull qy, ull qz,
                                     ull n0, ull n1, ull n2, ull cc) {
    asm("{\n\t"
        ".reg .b64 t;\n\t"
        ".reg .f32 lo, hi;\n\t"
        "fma.rn.f32x2 t, %2, %5, %8;\n\t"
        "fma.rn.f32x2 t, %3, %6, t;\n\t"
        "fma.rn.f32x2 t, %4, %7, t;\n\t"
        "mov.b64 {lo, hi}, t;\n\t"
        "min.f32 %0, %0, lo;\n\t"
        "min.f32 %1, %1, hi;\n\t"
        "}"
        : "+f"(ma), "+f"(mb)
        : "l"(qx), "l"(qy), "l"(qz), "l"(n0), "l"(n1), "l"(n2), "l"(cc));
}

// ---- Sort k1: histogram (64 blocks) ----------------------------------------
__global__ __launch_bounds__(256)
void hist_kernel(const float* __restrict__ p1, const float* __restrict__ p2) {
    const int db = blockIdx.x >> 3, chunk = blockIdx.x & 7;
    const float* __restrict__ P =
        ((db >> 2) ? p2 : p1) + (size_t)(db & 3) * NPTS * 3;
#pragma unroll
    for (int k = 0; k < 4; k++) {
        int i = chunk * 1024 + threadIdx.x + k * 256;
        atomicAdd(&g_hist[db][bucket(P[3 * i])], 1u);
    }
}

// ---- Sort k2: scan hist -> g_coff; zero hist; zero out[0] -------------------
__global__ __launch_bounds__(1024)
void scan_kernel(float* __restrict__ out) {
    __shared__ unsigned wtot[32];
    const int db = blockIdx.x, tid = threadIdx.x, lane = tid & 31, wid = tid >> 5;
    if (db == 0 && tid == 0) out[0] = 0.0f;

    const int base = tid * 8;
    unsigned h[8], loc[8], s = 0;
#pragma unroll
    for (int j = 0; j < 8; j++) {
        h[j] = g_hist[db][base + j];
        g_hist[db][base + j] = 0u;           // reset for next replay
        loc[j] = s; s += h[j];
    }
    unsigned v = s;
#pragma unroll
    for (int o = 1; o < 32; o <<= 1) {
        unsigned n = __shfl_up_sync(FULLMASK, v, o);
        if (lane >= o) v += n;
    }
    if (lane == 31) wtot[wid] = v;
    __syncthreads();
    if (tid < 32) {
        unsigned w = wtot[tid];
#pragma unroll
        for (int o = 1; o < 32; o <<= 1) {
            unsigned n = __shfl_up_sync(FULLMASK, w, o);
            if (tid >= o) w += n;
        }
        wtot[tid] = w;
    }
    __syncthreads();
    unsigned excl = v - s + (wid ? wtot[wid - 1] : 0u);
#pragma unroll
    for (int j = 0; j < 8; j++) g_coff[db][base + j] = (int)(excl + loc[j]);
}

// ---- Sort k3: scatter quads (64 blocks) -------------------------------------
__global__ __launch_bounds__(256)
void scatter_kernel(const float* __restrict__ p1, const float* __restrict__ p2) {
    const int db = blockIdx.x >> 3, chunk = blockIdx.x & 7;
    const float* __restrict__ P =
        ((db >> 2) ? p2 : p1) + (size_t)(db & 3) * NPTS * 3;
#pragma unroll
    for (int k = 0; k < 4; k++) {
        int i = chunk * 1024 + threadIdx.x + k * 256;
        float x = P[3 * i], y = P[3 * i + 1], z = P[3 * i + 2];
        int pos = atomicAdd(&g_coff[db][bucket(x)], 1);
        g_pts[db][pos] = make_float4(x, y, z, x * x + y * y + z * z);
    }
}

// ---- Pass A: per-query-tile upper bound; 256-target window staged in smem ---
__global__ __launch_bounds__(TILE)
void bound_kernel() {
    __shared__ __align__(16) float4 s_w[256];    // 4 KB window
    __shared__ float sred[TILE / 32];
    const int tid = threadIdx.x, lane = tid & 31, wid = tid >> 5;
    const int qt = blockIdx.x, db = blockIdx.y;
    const float4* __restrict__ Q = g_pts[db];
    const float4* __restrict__ T = g_pts[db ^ 4];

    const int ws = min(max(qt * TILE + TILE / 2 - 128, 0), NPTS - 256);
    s_w[tid] = T[ws + tid];                      // coalesced stage
    const float4 q = Q[qt * TILE + tid];
    const float m2x = -2.f * q.x, m2y = -2.f * q.y, m2z = -2.f * q.z;
    __syncthreads();

    float a0 = BIG, a1 = BIG, a2 = BIG, a3 = BIG;
#pragma unroll 4
    for (int j = 0; j < 256; j += 4) {           // warp-uniform j: LDS broadcast
        float4 t0 = s_w[j], t1 = s_w[j + 1], t2 = s_w[j + 2], t3 = s_w[j + 3];
        a0 = fminf(a0, fmaf(m2x, t0.x, fmaf(m2y, t0.y, fmaf(m2z, t0.z, t0.w))));
        a1 = fminf(a1, fmaf(m2x, t1.x, fmaf(m2y, t1.y, fmaf(m2z, t1.z, t1.w))));
        a2 = fminf(a2, fmaf(m2x, t2.x, fmaf(m2y, t2.y, fmaf(m2z, t2.z, t2.w))));
        a3 = fminf(a3, fmaf(m2x, t3.x, fmaf(m2y, t3.y, fmaf(m2z, t3.z, t3.w))));
    }
    float dm = fminf(fminf(a0, a1), fminf(a2, a3)) + q.w;   // d2 upper bound

#pragma unroll
    for (int o = 16; o; o >>= 1) dm = fmaxf(dm, __shfl_xor_sync(FULLMASK, dm, o));
    if (lane == 0) sred[wid] = dm;
    __syncthreads();
    if (tid == 0) {
        float m = 0.f;
#pragma unroll
        for (int i = 0; i < TILE / 32; i++) m = fmaxf(m, sred[i]);
        g_dmax[db][qt] = m;
    }
}

// ---- Pass B: R1 FFMA2 tile loop with block-level x-gap pruning ---------------
__global__ __launch_bounds__(PB_THREADS)
void tile_kernel() {
    const int qt = blockIdx.x >> 5, ts = blockIdx.x & 31;
    const int db = blockIdx.y;
    const float4* __restrict__ Q = g_pts[db];
    const float4* __restrict__ T = g_pts[db ^ 4];

    // Prune: x-gap between tiles vs tile bound (witness tile always survives).
    {
        const float qlo = Q[qt * TILE].x, qhi = Q[qt * TILE + TILE - 1].x;
        const float tlo = T[ts * TILE].x, thi = T[ts * TILE + TILE - 1].x;
        const float gap = fmaxf(0.f, fmaxf(tlo - qhi, qlo - thi));
        if (gap * gap > g_dmax[db][qt] * 1.0001f + 1e-6f) return;
    }

    __shared__ __align__(16) ull s_t[TILE / 2][4];   // 4 KB packed pairs
    const int tid = threadIdx.x;

    // Stage target tile: per pair -> (n0,n1,n2,cc) packed f32x2.
    {
        float4 ta = T[ts * TILE + 2 * tid];
        float4 tc = T[ts * TILE + 2 * tid + 1];
        ulonglong2* d = (ulonglong2*)s_t[tid];
        d[0] = make_ulonglong2(pack2(-2.0f * ta.x, -2.0f * tc.x),
                               pack2(-2.0f * ta.y, -2.0f * tc.y));
        d[1] = make_ulonglong2(pack2(-2.0f * ta.z, -2.0f * tc.z),
                               pack2(ta.w, tc.w));
    }

    ull qx[QPT], qy[QPT], qz[QPT];
    float ma[QPT], mb[QPT];
#pragma unroll
    for (int k = 0; k < QPT; k++) {
        const float4 q = Q[qt * TILE + tid + k * PB_THREADS];
        qx[k] = pack2(q.x, q.x);
        qy[k] = pack2(q.y, q.y);
        qz[k] = pack2(q.z, q.z);
        ma[k] = BIG; mb[k] = BIG;
    }
    __syncthreads();

    const ulonglong2* sm = (const ulonglong2*)&s_t[0][0];
#pragma unroll 4
    for (int j = 0; j < TILE / 2; j++) {
        ulonglong2 v0 = sm[2 * j];       // (n0,n1) LDS.128 broadcast
        ulonglong2 v1 = sm[2 * j + 1];   // (n2,cc)
#pragma unroll
        for (int k = 0; k < QPT; k++)
            step(ma[k], mb[k], qx[k], qy[k], qz[k], v0.x, v0.y, v1.x, v1.y);
    }

    unsigned* gk = g_key + db * NPTS + qt * TILE;
#pragma unroll
    for (int k = 0; k < QPT; k++)
        atomicMax(&gk[tid + k * PB_THREADS], enckey(fminf(ma[k], mb[k])));
}

// ---- Finish: add |q|^2, reduce, atomicAdd; reset keys ------------------------
__global__ __launch_bounds__(256)
void finish_kernel(float* __restrict__ out) {
    const int gid = blockIdx.x * 256 + threadIdx.x;
    const int db = gid >> 13, qi = gid & (NPTS - 1);
    float v = deckey(g_key[gid]) + g_pts[db][qi].w;
    g_key[gid] = 0u;

    __shared__ float sred[8];
#pragma unroll
    for (int o = 16; o; o >>= 1) v += __shfl_down_sync(FULLMASK, v, o);
    if ((threadIdx.x & 31) == 0) sred[threadIdx.x >> 5] = v;
    __syncthreads();
    if (threadIdx.x == 0) {
        float t = 0.f;
#pragma unroll
        for (int i = 0; i < 8; i++) t += sred[i];
        atomicAdd(out, t);
    }
}

extern "C" void kernel_launch(void* const* d_in, const int* in_sizes, int n_in,
                              void* d_out, int out_size) {
    const float* p1 = (const float*)d_in[0];
    const float* p2 = (const float*)d_in[1];
    float* out = (float*)d_out;

    hist_kernel<<<64, 256>>>(p1, p2);
    scan_kernel<<<8, 1024>>>(out);
    scatter_kernel<<<64, 256>>>(p1, p2);
    bound_kernel<<<dim3(NTILE, 8), TILE>>>();
    tile_kernel<<<dim3(NTILE * NTILE, 8), PB_THREADS>>>();
    finish_kernel<<<TOTQ / 256, 256>>>(out);
}